// round 1
// baseline (speedup 1.0000x reference)
#include <cuda_runtime.h>
#include <cstddef>

#define NHAND 21
#define DMODEL 128
#define FIN 256
#define FOUT 512
#define ODIM 3
#define NTHREADS 128

struct __align__(16) Smem {
    float X[NHAND][FIN];       // layer-1 input staging      (21504 B)
    float Buf[NHAND][DMODEL];  // H1, then A3@H2             (10752 B)
    float A1s[NHAND][24];      // padded rows (zeros 21..23)
    float A2s[NHAND][24];
    float A3s[NHAND][24];
    float b1s[DMODEL];
    float b2s[DMODEL];
    float fcWs[FOUT][ODIM];
    float fcbs[ODIM];
    float Out[NHAND][ODIM];
};

__global__ void __launch_bounds__(NTHREADS) handnet_fused_kernel(
    const float* __restrict__ x,
    const float* __restrict__ A1, const float* __restrict__ A2, const float* __restrict__ A3,
    const float* __restrict__ W1, const float* __restrict__ b1,
    const float* __restrict__ W2, const float* __restrict__ b2,
    const float* __restrict__ W3, const float* __restrict__ b3,
    const float* __restrict__ fcW, const float* __restrict__ fcb,
    float* __restrict__ x3_out, float* __restrict__ fc_out)
{
    __shared__ Smem s;
    const int o = threadIdx.x;           // output channel 0..127
    const int b = blockIdx.x;            // batch element

    // ---------------- cooperative loads ----------------
    {
        const float4* xg = reinterpret_cast<const float4*>(x + (size_t)b * NHAND * FIN);
        float4* sx4 = reinterpret_cast<float4*>(&s.X[0][0]);
        #pragma unroll
        for (int i = 0; i < 11; i++) {
            int idx = o + i * NTHREADS;
            if (idx < NHAND * FIN / 4) sx4[idx] = xg[idx];
        }
        // A matrices, padded to 24 cols with zeros
        for (int idx = o; idx < NHAND * 24; idx += NTHREADS) {
            int n = idx / 24, m = idx % 24;
            float a1 = 0.f, a2 = 0.f, a3 = 0.f;
            if (m < NHAND) {
                a1 = A1[n * NHAND + m];
                a2 = A2[n * NHAND + m];
                a3 = A3[n * NHAND + m];
            }
            s.A1s[n][m] = a1; s.A2s[n][m] = a2; s.A3s[n][m] = a3;
        }
        s.b1s[o] = b1[o];
        s.b2s[o] = b2[o];
        for (int idx = o; idx < FOUT * ODIM; idx += NTHREADS)
            (&s.fcWs[0][0])[idx] = fcW[idx];
        if (o < ODIM) s.fcbs[o] = fcb[o];
        for (int idx = o; idx < NHAND * ODIM; idx += NTHREADS)
            (&s.Out[0][0])[idx] = 0.f;
    }
    __syncthreads();

    float acc[NHAND];

    // ---------------- layer 1: G1 = X @ W1 (K=256) ----------------
    #pragma unroll
    for (int m = 0; m < NHAND; m++) acc[m] = 0.f;
    for (int f0 = 0; f0 < FIN; f0 += 4) {
        float w0 = __ldg(&W1[(f0 + 0) * DMODEL + o]);
        float w1 = __ldg(&W1[(f0 + 1) * DMODEL + o]);
        float w2 = __ldg(&W1[(f0 + 2) * DMODEL + o]);
        float w3 = __ldg(&W1[(f0 + 3) * DMODEL + o]);
        #pragma unroll
        for (int m = 0; m < NHAND; m++) {
            float4 xv = *reinterpret_cast<const float4*>(&s.X[m][f0]);
            acc[m] = fmaf(xv.x, w0, acc[m]);
            acc[m] = fmaf(xv.y, w1, acc[m]);
            acc[m] = fmaf(xv.z, w2, acc[m]);
            acc[m] = fmaf(xv.w, w3, acc[m]);
        }
    }
    // A1-mix + bias + relu -> Buf (H1)
    {
        float bias = s.b1s[o];
        #pragma unroll
        for (int n = 0; n < NHAND; n++) {
            float h = bias;
            #pragma unroll
            for (int m4 = 0; m4 < 5; m4++) {
                float4 a = *reinterpret_cast<const float4*>(&s.A1s[n][m4 * 4]);
                h = fmaf(a.x, acc[m4 * 4 + 0], h);
                h = fmaf(a.y, acc[m4 * 4 + 1], h);
                h = fmaf(a.z, acc[m4 * 4 + 2], h);
                h = fmaf(a.w, acc[m4 * 4 + 3], h);
            }
            h = fmaf(s.A1s[n][20], acc[20], h);
            s.Buf[n][o] = fmaxf(h, 0.f);
        }
    }
    __syncthreads();

    // ---------------- layer 2: G2 = H1 @ W2 (K=128) ----------------
    #pragma unroll
    for (int m = 0; m < NHAND; m++) acc[m] = 0.f;
    for (int f0 = 0; f0 < DMODEL; f0 += 4) {
        float w0 = __ldg(&W2[(f0 + 0) * DMODEL + o]);
        float w1 = __ldg(&W2[(f0 + 1) * DMODEL + o]);
        float w2 = __ldg(&W2[(f0 + 2) * DMODEL + o]);
        float w3 = __ldg(&W2[(f0 + 3) * DMODEL + o]);
        #pragma unroll
        for (int m = 0; m < NHAND; m++) {
            float4 hv = *reinterpret_cast<const float4*>(&s.Buf[m][f0]);
            acc[m] = fmaf(hv.x, w0, acc[m]);
            acc[m] = fmaf(hv.y, w1, acc[m]);
            acc[m] = fmaf(hv.z, w2, acc[m]);
            acc[m] = fmaf(hv.w, w3, acc[m]);
        }
    }
    __syncthreads();   // everyone done reading Buf before we overwrite it

    // A2-mix + bias + relu -> h2 (regs), then A3-mix -> Buf
    {
        float h2[NHAND];
        float bias = s.b2s[o];
        #pragma unroll
        for (int n = 0; n < NHAND; n++) {
            float h = bias;
            #pragma unroll
            for (int m4 = 0; m4 < 5; m4++) {
                float4 a = *reinterpret_cast<const float4*>(&s.A2s[n][m4 * 4]);
                h = fmaf(a.x, acc[m4 * 4 + 0], h);
                h = fmaf(a.y, acc[m4 * 4 + 1], h);
                h = fmaf(a.z, acc[m4 * 4 + 2], h);
                h = fmaf(a.w, acc[m4 * 4 + 3], h);
            }
            h = fmaf(s.A2s[n][20], acc[20], h);
            h2[n] = fmaxf(h, 0.f);
        }
        #pragma unroll
        for (int n = 0; n < NHAND; n++) {
            float g = 0.f;
            #pragma unroll
            for (int m4 = 0; m4 < 5; m4++) {
                float4 a = *reinterpret_cast<const float4*>(&s.A3s[n][m4 * 4]);
                g = fmaf(a.x, h2[m4 * 4 + 0], g);
                g = fmaf(a.y, h2[m4 * 4 + 1], g);
                g = fmaf(a.z, h2[m4 * 4 + 2], g);
                g = fmaf(a.w, h2[m4 * 4 + 3], g);
            }
            g = fmaf(s.A3s[n][20], h2[20], g);
            s.Buf[n][o] = g;      // AH2 (pre-W3), no relu/bias here
        }
    }
    __syncthreads();

    // ---------------- layer 3: x3 = relu(AH2 @ W3 + b3), fused fc ----------------
    float bb3[4];
    #pragma unroll
    for (int c = 0; c < 4; c++) bb3[c] = __ldg(&b3[o + 128 * c]);

    for (int mc = 0; mc < NHAND; mc += 7) {     // 3 row chunks of 7
        float a3c[7][4];
        #pragma unroll
        for (int mm = 0; mm < 7; mm++)
            #pragma unroll
            for (int c = 0; c < 4; c++) a3c[mm][c] = bb3[c];

        for (int f0 = 0; f0 < DMODEL; f0 += 4) {
            float w[4][4];
            #pragma unroll
            for (int fi = 0; fi < 4; fi++)
                #pragma unroll
                for (int c = 0; c < 4; c++)
                    w[fi][c] = __ldg(&W3[(f0 + fi) * FOUT + o + 128 * c]);
            #pragma unroll
            for (int mm = 0; mm < 7; mm++) {
                float4 hv = *reinterpret_cast<const float4*>(&s.Buf[mc + mm][f0]);
                #pragma unroll
                for (int c = 0; c < 4; c++) {
                    a3c[mm][c] = fmaf(hv.x, w[0][c], a3c[mm][c]);
                    a3c[mm][c] = fmaf(hv.y, w[1][c], a3c[mm][c]);
                    a3c[mm][c] = fmaf(hv.z, w[2][c], a3c[mm][c]);
                    a3c[mm][c] = fmaf(hv.w, w[3][c], a3c[mm][c]);
                }
            }
        }
        // relu + store x3 + fc partials
        #pragma unroll
        for (int mm = 0; mm < 7; mm++) {
            int m = mc + mm;
            float p0 = 0.f, p1 = 0.f, p2 = 0.f;
            #pragma unroll
            for (int c = 0; c < 4; c++) {
                float v = fmaxf(a3c[mm][c], 0.f);
                int col = o + 128 * c;
                x3_out[((size_t)b * NHAND + m) * FOUT + col] = v;
                p0 = fmaf(v, s.fcWs[col][0], p0);
                p1 = fmaf(v, s.fcWs[col][1], p1);
                p2 = fmaf(v, s.fcWs[col][2], p2);
            }
            #pragma unroll
            for (int off = 16; off > 0; off >>= 1) {
                p0 += __shfl_down_sync(0xffffffffu, p0, off);
                p1 += __shfl_down_sync(0xffffffffu, p1, off);
                p2 += __shfl_down_sync(0xffffffffu, p2, off);
            }
            if ((o & 31) == 0) {
                atomicAdd(&s.Out[m][0], p0);
                atomicAdd(&s.Out[m][1], p1);
                atomicAdd(&s.Out[m][2], p2);
            }
        }
    }
    __syncthreads();

    // ---------------- write fc output ----------------
    if (o < NHAND * ODIM) {
        int n = o / ODIM, j = o % ODIM;
        fc_out[((size_t)b * NHAND + n) * ODIM + j] = s.Out[n][j] + s.fcbs[j];
    }
}

extern "C" void kernel_launch(void* const* d_in, const int* in_sizes, int n_in,
                              void* d_out, int out_size)
{
    const float* x   = (const float*)d_in[0];
    const float* A1  = (const float*)d_in[1];
    const float* A2  = (const float*)d_in[2];
    const float* A3  = (const float*)d_in[3];
    const float* W1  = (const float*)d_in[4];
    const float* b1  = (const float*)d_in[5];
    const float* W2  = (const float*)d_in[6];
    const float* b2  = (const float*)d_in[7];
    const float* W3  = (const float*)d_in[8];
    const float* b3  = (const float*)d_in[9];
    const float* fcW = (const float*)d_in[10];
    const float* fcb = (const float*)d_in[11];

    const int B = in_sizes[0] / (NHAND * FIN);
    float* x3_out = (float*)d_out;
    float* fc_out = x3_out + (size_t)B * NHAND * FOUT;

    handnet_fused_kernel<<<B, NTHREADS>>>(x, A1, A2, A3, W1, b1, W2, b2,
                                          W3, b3, fcW, fcb, x3_out, fc_out);
}

// round 2
// speedup vs baseline: 1.1743x; 1.1743x over previous
#include <cuda_runtime.h>
#include <cstddef>

#define NHAND 21
#define DMODEL 128
#define FIN 256
#define FOUT 512
#define ODIM 3
#define NTHREADS 128

typedef unsigned long long ull;

__device__ __forceinline__ ull ffma2(ull a, ull b, ull c) {
    ull d;
    asm("fma.rn.f32x2 %0, %1, %2, %3;" : "=l"(d) : "l"(a), "l"(b), "l"(c));
    return d;
}
__device__ __forceinline__ ull pack2(float lo, float hi) {
    ull d;
    asm("mov.b64 %0, {%1, %2};" : "=l"(d) : "f"(lo), "f"(hi));
    return d;
}
__device__ __forceinline__ float2 unpack2(ull v) {
    float lo, hi;
    asm("mov.b64 {%0, %1}, %2;" : "=f"(lo), "=f"(hi) : "l"(v));
    return make_float2(lo, hi);
}

struct __align__(16) Smem {
    float X[NHAND][FIN];        // layer-1 input staging (21504 B)
    float Buf[NHAND][DMODEL];   // H1, then A3@H2        (10752 B)
    float2 Apk[3][NHAND][12];   // A rows packed in m-pairs, zero padded (6048 B)
    float b1s[DMODEL];
    float b2s[DMODEL];
    float fcWs[FOUT][ODIM];     // 6144 B
    float fcbs[ODIM];
    float Out[NHAND][ODIM];
};

__global__ void __launch_bounds__(NTHREADS, 4) handnet_fused_kernel(
    const float* __restrict__ x,
    const float* __restrict__ A1, const float* __restrict__ A2, const float* __restrict__ A3,
    const float* __restrict__ W1, const float* __restrict__ b1,
    const float* __restrict__ W2, const float* __restrict__ b2,
    const float* __restrict__ W3, const float* __restrict__ b3,
    const float* __restrict__ fcW, const float* __restrict__ fcb,
    float* __restrict__ x3_out, float* __restrict__ fc_out)
{
    __shared__ Smem s;
    const int o = threadIdx.x;           // output channel 0..127
    const int b = blockIdx.x;            // batch element

    // ---------------- cooperative loads ----------------
    {
        const float4* xg = reinterpret_cast<const float4*>(x + (size_t)b * NHAND * FIN);
        float4* sx4 = reinterpret_cast<float4*>(&s.X[0][0]);
        #pragma unroll
        for (int i = 0; i < 11; i++) {
            int idx = o + i * NTHREADS;
            if (idx < NHAND * FIN / 4) sx4[idx] = xg[idx];
        }
        // A matrices packed in m-pairs (12 pairs, zero padded past m=20)
        for (int idx = o; idx < NHAND * 12; idx += NTHREADS) {
            int n = idx / 12, mm = idx % 12;
            int m0 = 2 * mm, m1 = 2 * mm + 1;
            float a1x = (m0 < NHAND) ? A1[n * NHAND + m0] : 0.f;
            float a1y = (m1 < NHAND) ? A1[n * NHAND + m1] : 0.f;
            float a2x = (m0 < NHAND) ? A2[n * NHAND + m0] : 0.f;
            float a2y = (m1 < NHAND) ? A2[n * NHAND + m1] : 0.f;
            float a3x = (m0 < NHAND) ? A3[n * NHAND + m0] : 0.f;
            float a3y = (m1 < NHAND) ? A3[n * NHAND + m1] : 0.f;
            s.Apk[0][n][mm] = make_float2(a1x, a1y);
            s.Apk[1][n][mm] = make_float2(a2x, a2y);
            s.Apk[2][n][mm] = make_float2(a3x, a3y);
        }
        s.b1s[o] = b1[o];
        s.b2s[o] = b2[o];
        for (int idx = o; idx < FOUT * ODIM; idx += NTHREADS)
            (&s.fcWs[0][0])[idx] = fcW[idx];
        if (o < ODIM) s.fcbs[o] = fcb[o];
        for (int idx = o; idx < NHAND * ODIM; idx += NTHREADS)
            (&s.Out[0][0])[idx] = 0.f;
    }
    __syncthreads();

    ull acc2[NHAND];
    float as[NHAND];
    ull P[11];

    // ---------------- layer 1: G1 = X @ W1 (K=256, k-packed) ----------------
    #pragma unroll
    for (int m = 0; m < NHAND; m++) acc2[m] = 0ull;
    for (int f0 = 0; f0 < FIN; f0 += 4) {
        const float* wr = W1 + f0 * DMODEL + o;
        float w0 = __ldg(wr);
        float w1 = __ldg(wr + DMODEL);
        float w2 = __ldg(wr + 2 * DMODEL);
        float w3 = __ldg(wr + 3 * DMODEL);
        ull wp01 = pack2(w0, w1), wp23 = pack2(w2, w3);
        #pragma unroll
        for (int m = 0; m < NHAND; m++) {
            ulonglong2 xv = *reinterpret_cast<const ulonglong2*>(&s.X[m][f0]);
            acc2[m] = ffma2(xv.x, wp01, acc2[m]);
            acc2[m] = ffma2(xv.y, wp23, acc2[m]);
        }
    }
    // horizontal add + repack for the mix
    #pragma unroll
    for (int m = 0; m < NHAND; m++) { float2 t = unpack2(acc2[m]); as[m] = t.x + t.y; }
    #pragma unroll
    for (int mm = 0; mm < 10; mm++) P[mm] = pack2(as[2 * mm], as[2 * mm + 1]);
    P[10] = pack2(as[20], 0.f);

    // A1-mix + bias + relu -> Buf (H1)
    {
        float bias = s.b1s[o];
        #pragma unroll
        for (int n = 0; n < NHAND; n++) {
            ull acc = 0ull;
            #pragma unroll
            for (int mm = 0; mm < 11; mm++) {
                float2 a = s.Apk[0][n][mm];
                acc = ffma2(pack2(a.x, a.y), P[mm], acc);
            }
            float2 t = unpack2(acc);
            s.Buf[n][o] = fmaxf(t.x + t.y + bias, 0.f);
        }
    }
    __syncthreads();

    // ---------------- layer 2: G2 = H1 @ W2 (K=128, k-packed) ----------------
    #pragma unroll
    for (int m = 0; m < NHAND; m++) acc2[m] = 0ull;
    for (int f0 = 0; f0 < DMODEL; f0 += 4) {
        const float* wr = W2 + f0 * DMODEL + o;
        float w0 = __ldg(wr);
        float w1 = __ldg(wr + DMODEL);
        float w2 = __ldg(wr + 2 * DMODEL);
        float w3 = __ldg(wr + 3 * DMODEL);
        ull wp01 = pack2(w0, w1), wp23 = pack2(w2, w3);
        #pragma unroll
        for (int m = 0; m < NHAND; m++) {
            ulonglong2 hv = *reinterpret_cast<const ulonglong2*>(&s.Buf[m][f0]);
            acc2[m] = ffma2(hv.x, wp01, acc2[m]);
            acc2[m] = ffma2(hv.y, wp23, acc2[m]);
        }
    }
    __syncthreads();   // done reading Buf before overwrite

    // A2-mix + bias + relu -> h2 (regs), then A3-mix -> Buf
    {
        #pragma unroll
        for (int m = 0; m < NHAND; m++) { float2 t = unpack2(acc2[m]); as[m] = t.x + t.y; }
        #pragma unroll
        for (int mm = 0; mm < 10; mm++) P[mm] = pack2(as[2 * mm], as[2 * mm + 1]);
        P[10] = pack2(as[20], 0.f);

        float h2[NHAND];
        float bias = s.b2s[o];
        #pragma unroll
        for (int n = 0; n < NHAND; n++) {
            ull acc = 0ull;
            #pragma unroll
            for (int mm = 0; mm < 11; mm++) {
                float2 a = s.Apk[1][n][mm];
                acc = ffma2(pack2(a.x, a.y), P[mm], acc);
            }
            float2 t = unpack2(acc);
            h2[n] = fmaxf(t.x + t.y + bias, 0.f);
        }
        #pragma unroll
        for (int mm = 0; mm < 10; mm++) P[mm] = pack2(h2[2 * mm], h2[2 * mm + 1]);
        P[10] = pack2(h2[20], 0.f);
        #pragma unroll
        for (int n = 0; n < NHAND; n++) {
            ull acc = 0ull;
            #pragma unroll
            for (int mm = 0; mm < 11; mm++) {
                float2 a = s.Apk[2][n][mm];
                acc = ffma2(pack2(a.x, a.y), P[mm], acc);
            }
            float2 t = unpack2(acc);
            s.Buf[n][o] = t.x + t.y;   // AH2 (pre-W3), no relu/bias here
        }
    }
    __syncthreads();

    // ---------------- layer 3: x3 = relu(AH2 @ W3 + b3), fused fc ----------------
    float bb3[4];
    #pragma unroll
    for (int c = 0; c < 4; c++) bb3[c] = __ldg(&b3[o + 128 * c]);

    for (int mc = 0; mc < NHAND; mc += 7) {     // 3 row chunks of 7
        ull a3c[7][4];
        #pragma unroll
        for (int mm = 0; mm < 7; mm++)
            #pragma unroll
            for (int c = 0; c < 4; c++) a3c[mm][c] = 0ull;

        for (int f0 = 0; f0 < DMODEL; f0 += 4) {
            ull wp[4][2];
            #pragma unroll
            for (int c = 0; c < 4; c++) {
                const float* wr = W3 + f0 * FOUT + o + 128 * c;
                float w0 = __ldg(wr);
                float w1 = __ldg(wr + FOUT);
                float w2 = __ldg(wr + 2 * FOUT);
                float w3 = __ldg(wr + 3 * FOUT);
                wp[c][0] = pack2(w0, w1);
                wp[c][1] = pack2(w2, w3);
            }
            #pragma unroll
            for (int mm = 0; mm < 7; mm++) {
                ulonglong2 hv = *reinterpret_cast<const ulonglong2*>(&s.Buf[mc + mm][f0]);
                #pragma unroll
                for (int c = 0; c < 4; c++) {
                    a3c[mm][c] = ffma2(hv.x, wp[c][0], a3c[mm][c]);
                    a3c[mm][c] = ffma2(hv.y, wp[c][1], a3c[mm][c]);
                }
            }
        }
        // relu + store x3 + fc partials
        #pragma unroll
        for (int mm = 0; mm < 7; mm++) {
            int m = mc + mm;
            float p0 = 0.f, p1 = 0.f, p2 = 0.f;
            #pragma unroll
            for (int c = 0; c < 4; c++) {
                float2 t = unpack2(a3c[mm][c]);
                float v = fmaxf(t.x + t.y + bb3[c], 0.f);
                int col = o + 128 * c;
                x3_out[((size_t)b * NHAND + m) * FOUT + col] = v;
                p0 = fmaf(v, s.fcWs[col][0], p0);
                p1 = fmaf(v, s.fcWs[col][1], p1);
                p2 = fmaf(v, s.fcWs[col][2], p2);
            }
            #pragma unroll
            for (int off = 16; off > 0; off >>= 1) {
                p0 += __shfl_down_sync(0xffffffffu, p0, off);
                p1 += __shfl_down_sync(0xffffffffu, p1, off);
                p2 += __shfl_down_sync(0xffffffffu, p2, off);
            }
            if ((o & 31) == 0) {
                atomicAdd(&s.Out[m][0], p0);
                atomicAdd(&s.Out[m][1], p1);
                atomicAdd(&s.Out[m][2], p2);
            }
        }
    }
    __syncthreads();

    // ---------------- write fc output ----------------
    if (o < NHAND * ODIM) {
        int n = o / ODIM, j = o % ODIM;
        fc_out[((size_t)b * NHAND + n) * ODIM + j] = s.Out[n][j] + s.fcbs[j];
    }
}

extern "C" void kernel_launch(void* const* d_in, const int* in_sizes, int n_in,
                              void* d_out, int out_size)
{
    const float* x   = (const float*)d_in[0];
    const float* A1  = (const float*)d_in[1];
    const float* A2  = (const float*)d_in[2];
    const float* A3  = (const float*)d_in[3];
    const float* W1  = (const float*)d_in[4];
    const float* b1  = (const float*)d_in[5];
    const float* W2  = (const float*)d_in[6];
    const float* b2  = (const float*)d_in[7];
    const float* W3  = (const float*)d_in[8];
    const float* b3  = (const float*)d_in[9];
    const float* fcW = (const float*)d_in[10];
    const float* fcb = (const float*)d_in[11];

    const int B = in_sizes[0] / (NHAND * FIN);
    float* x3_out = (float*)d_out;
    float* fc_out = x3_out + (size_t)B * NHAND * FOUT;

    handnet_fused_kernel<<<B, NTHREADS>>>(x, A1, A2, A3, W1, b1, W2, b2,
                                          W3, b3, fcW, fcb, x3_out, fc_out);
}

// round 3
// speedup vs baseline: 1.1763x; 1.0017x over previous
#include <cuda_runtime.h>
#include <cstddef>

#define NHAND 21
#define DMODEL 128
#define FIN 256
#define FOUT 512
#define ODIM 3
#define NTHREADS 128

typedef unsigned long long ull;

__device__ __forceinline__ ull ffma2(ull a, ull b, ull c) {
    ull d;
    asm("fma.rn.f32x2 %0, %1, %2, %3;" : "=l"(d) : "l"(a), "l"(b), "l"(c));
    return d;
}
__device__ __forceinline__ ull pack2(float lo, float hi) {
    ull d;
    asm("mov.b64 %0, {%1, %2};" : "=l"(d) : "f"(lo), "f"(hi));
    return d;
}
__device__ __forceinline__ float2 unpack2(ull v) {
    float lo, hi;
    asm("mov.b64 {%0, %1}, %2;" : "=f"(lo), "=f"(hi) : "l"(v));
    return make_float2(lo, hi);
}

struct __align__(16) Smem {
    float X[NHAND][FIN];        // layer-1 input staging (21504 B)
    float Buf[NHAND][DMODEL];   // H1, then A3@H2        (10752 B)
    float2 Apk[3][NHAND][12];   // A rows packed in m-pairs, zero padded (6048 B)
    float b1s[DMODEL];
    float b2s[DMODEL];
    float fcWs[FOUT][ODIM];     // 6144 B
    float fcbs[ODIM];
    float Out[NHAND][ODIM];
};

__global__ void __launch_bounds__(NTHREADS, 4) handnet_fused_kernel(
    const float* __restrict__ x,
    const float* __restrict__ A1, const float* __restrict__ A2, const float* __restrict__ A3,
    const float* __restrict__ W1, const float* __restrict__ b1,
    const float* __restrict__ W2, const float* __restrict__ b2,
    const float* __restrict__ W3, const float* __restrict__ b3,
    const float* __restrict__ fcW, const float* __restrict__ fcb,
    float* __restrict__ x3_out, float* __restrict__ fc_out)
{
    __shared__ Smem s;
    const int o = threadIdx.x;           // output channel 0..127
    const int b = blockIdx.x;            // batch element

    // ---------------- cooperative loads ----------------
    {
        const float4* xg = reinterpret_cast<const float4*>(x + (size_t)b * NHAND * FIN);
        float4* sx4 = reinterpret_cast<float4*>(&s.X[0][0]);
        #pragma unroll
        for (int i = 0; i < 11; i++) {
            int idx = o + i * NTHREADS;
            if (idx < NHAND * FIN / 4) sx4[idx] = xg[idx];
        }
        // A matrices packed in m-pairs (12 pairs, zero padded past m=20)
        for (int idx = o; idx < NHAND * 12; idx += NTHREADS) {
            int n = idx / 12, mm = idx % 12;
            int m0 = 2 * mm, m1 = 2 * mm + 1;
            float a1x = (m0 < NHAND) ? A1[n * NHAND + m0] : 0.f;
            float a1y = (m1 < NHAND) ? A1[n * NHAND + m1] : 0.f;
            float a2x = (m0 < NHAND) ? A2[n * NHAND + m0] : 0.f;
            float a2y = (m1 < NHAND) ? A2[n * NHAND + m1] : 0.f;
            float a3x = (m0 < NHAND) ? A3[n * NHAND + m0] : 0.f;
            float a3y = (m1 < NHAND) ? A3[n * NHAND + m1] : 0.f;
            s.Apk[0][n][mm] = make_float2(a1x, a1y);
            s.Apk[1][n][mm] = make_float2(a2x, a2y);
            s.Apk[2][n][mm] = make_float2(a3x, a3y);
        }
        s.b1s[o] = b1[o];
        s.b2s[o] = b2[o];
        for (int idx = o; idx < FOUT * ODIM; idx += NTHREADS)
            (&s.fcWs[0][0])[idx] = fcW[idx];
        if (o < ODIM) s.fcbs[o] = fcb[o];
        for (int idx = o; idx < NHAND * ODIM; idx += NTHREADS)
            (&s.Out[0][0])[idx] = 0.f;
    }
    __syncthreads();

    ull acc2[NHAND];
    float as[NHAND];
    ull P[11];

    // ---------------- layer 1: G1 = X @ W1 (K=256, k-packed) ----------------
    #pragma unroll
    for (int m = 0; m < NHAND; m++) acc2[m] = 0ull;
    for (int f0 = 0; f0 < FIN; f0 += 4) {
        const float* wr = W1 + f0 * DMODEL + o;
        float w0 = __ldg(wr);
        float w1 = __ldg(wr + DMODEL);
        float w2 = __ldg(wr + 2 * DMODEL);
        float w3 = __ldg(wr + 3 * DMODEL);
        ull wp01 = pack2(w0, w1), wp23 = pack2(w2, w3);
        #pragma unroll
        for (int m = 0; m < NHAND; m++) {
            ulonglong2 xv = *reinterpret_cast<const ulonglong2*>(&s.X[m][f0]);
            acc2[m] = ffma2(xv.x, wp01, acc2[m]);
            acc2[m] = ffma2(xv.y, wp23, acc2[m]);
        }
    }
    // horizontal add + repack for the mix
    #pragma unroll
    for (int m = 0; m < NHAND; m++) { float2 t = unpack2(acc2[m]); as[m] = t.x + t.y; }
    #pragma unroll
    for (int mm = 0; mm < 10; mm++) P[mm] = pack2(as[2 * mm], as[2 * mm + 1]);
    P[10] = pack2(as[20], 0.f);

    // A1-mix + bias + relu -> Buf (H1)
    {
        float bias = s.b1s[o];
        #pragma unroll
        for (int n = 0; n < NHAND; n++) {
            ull acc = 0ull;
            #pragma unroll
            for (int mm = 0; mm < 11; mm++) {
                float2 a = s.Apk[0][n][mm];
                acc = ffma2(pack2(a.x, a.y), P[mm], acc);
            }
            float2 t = unpack2(acc);
            s.Buf[n][o] = fmaxf(t.x + t.y + bias, 0.f);
        }
    }
    __syncthreads();

    // ---------------- layer 2: G2 = H1 @ W2 (K=128, k-packed) ----------------
    #pragma unroll
    for (int m = 0; m < NHAND; m++) acc2[m] = 0ull;
    for (int f0 = 0; f0 < DMODEL; f0 += 4) {
        const float* wr = W2 + f0 * DMODEL + o;
        float w0 = __ldg(wr);
        float w1 = __ldg(wr + DMODEL);
        float w2 = __ldg(wr + 2 * DMODEL);
        float w3 = __ldg(wr + 3 * DMODEL);
        ull wp01 = pack2(w0, w1), wp23 = pack2(w2, w3);
        #pragma unroll
        for (int m = 0; m < NHAND; m++) {
            ulonglong2 hv = *reinterpret_cast<const ulonglong2*>(&s.Buf[m][f0]);
            acc2[m] = ffma2(hv.x, wp01, acc2[m]);
            acc2[m] = ffma2(hv.y, wp23, acc2[m]);
        }
    }
    __syncthreads();   // done reading Buf before overwrite

    // A2-mix + bias + relu -> h2 (regs), then A3-mix -> Buf
    {
        #pragma unroll
        for (int m = 0; m < NHAND; m++) { float2 t = unpack2(acc2[m]); as[m] = t.x + t.y; }
        #pragma unroll
        for (int mm = 0; mm < 10; mm++) P[mm] = pack2(as[2 * mm], as[2 * mm + 1]);
        P[10] = pack2(as[20], 0.f);

        float h2[NHAND];
        float bias = s.b2s[o];
        #pragma unroll
        for (int n = 0; n < NHAND; n++) {
            ull acc = 0ull;
            #pragma unroll
            for (int mm = 0; mm < 11; mm++) {
                float2 a = s.Apk[1][n][mm];
                acc = ffma2(pack2(a.x, a.y), P[mm], acc);
            }
            float2 t = unpack2(acc);
            h2[n] = fmaxf(t.x + t.y + bias, 0.f);
        }
        #pragma unroll
        for (int mm = 0; mm < 10; mm++) P[mm] = pack2(h2[2 * mm], h2[2 * mm + 1]);
        P[10] = pack2(h2[20], 0.f);
        #pragma unroll
        for (int n = 0; n < NHAND; n++) {
            ull acc = 0ull;
            #pragma unroll
            for (int mm = 0; mm < 11; mm++) {
                float2 a = s.Apk[2][n][mm];
                acc = ffma2(pack2(a.x, a.y), P[mm], acc);
            }
            float2 t = unpack2(acc);
            s.Buf[n][o] = t.x + t.y;   // AH2 (pre-W3), no relu/bias here
        }
    }
    __syncthreads();

    // ---------------- layer 3: x3 = relu(AH2 @ W3 + b3), fused fc ----------------
    float bb3[4];
    #pragma unroll
    for (int c = 0; c < 4; c++) bb3[c] = __ldg(&b3[o + 128 * c]);

    for (int mc = 0; mc < NHAND; mc += 7) {     // 3 row chunks of 7
        ull a3c[7][4];
        #pragma unroll
        for (int mm = 0; mm < 7; mm++)
            #pragma unroll
            for (int c = 0; c < 4; c++) a3c[mm][c] = 0ull;

        for (int f0 = 0; f0 < DMODEL; f0 += 4) {
            ull wp[4][2];
            #pragma unroll
            for (int c = 0; c < 4; c++) {
                const float* wr = W3 + f0 * FOUT + o + 128 * c;
                float w0 = __ldg(wr);
                float w1 = __ldg(wr + FOUT);
                float w2 = __ldg(wr + 2 * FOUT);
                float w3 = __ldg(wr + 3 * FOUT);
                wp[c][0] = pack2(w0, w1);
                wp[c][1] = pack2(w2, w3);
            }
            #pragma unroll
            for (int mm = 0; mm < 7; mm++) {
                ulonglong2 hv = *reinterpret_cast<const ulonglong2*>(&s.Buf[mc + mm][f0]);
                #pragma unroll
                for (int c = 0; c < 4; c++) {
                    a3c[mm][c] = ffma2(hv.x, wp[c][0], a3c[mm][c]);
                    a3c[mm][c] = ffma2(hv.y, wp[c][1], a3c[mm][c]);
                }
            }
        }
        // relu + store x3 + fc partials
        #pragma unroll
        for (int mm = 0; mm < 7; mm++) {
            int m = mc + mm;
            float p0 = 0.f, p1 = 0.f, p2 = 0.f;
            #pragma unroll
            for (int c = 0; c < 4; c++) {
                float2 t = unpack2(a3c[mm][c]);
                float v = fmaxf(t.x + t.y + bb3[c], 0.f);
                int col = o + 128 * c;
                x3_out[((size_t)b * NHAND + m) * FOUT + col] = v;
                p0 = fmaf(v, s.fcWs[col][0], p0);
                p1 = fmaf(v, s.fcWs[col][1], p1);
                p2 = fmaf(v, s.fcWs[col][2], p2);
            }
            #pragma unroll
            for (int off = 16; off > 0; off >>= 1) {
                p0 += __shfl_down_sync(0xffffffffu, p0, off);
                p1 += __shfl_down_sync(0xffffffffu, p1, off);
                p2 += __shfl_down_sync(0xffffffffu, p2, off);
            }
            if ((o & 31) == 0) {
                atomicAdd(&s.Out[m][0], p0);
                atomicAdd(&s.Out[m][1], p1);
                atomicAdd(&s.Out[m][2], p2);
            }
        }
    }
    __syncthreads();

    // ---------------- write fc output ----------------
    if (o < NHAND * ODIM) {
        int n = o / ODIM, j = o % ODIM;
        fc_out[((size_t)b * NHAND + n) * ODIM + j] = s.Out[n][j] + s.fcbs[j];
    }
}

extern "C" void kernel_launch(void* const* d_in, const int* in_sizes, int n_in,
                              void* d_out, int out_size)
{
    const float* x   = (const float*)d_in[0];
    const float* A1  = (const float*)d_in[1];
    const float* A2  = (const float*)d_in[2];
    const float* A3  = (const float*)d_in[3];
    const float* W1  = (const float*)d_in[4];
    const float* b1  = (const float*)d_in[5];
    const float* W2  = (const float*)d_in[6];
    const float* b2  = (const float*)d_in[7];
    const float* W3  = (const float*)d_in[8];
    const float* b3  = (const float*)d_in[9];
    const float* fcW = (const float*)d_in[10];
    const float* fcb = (const float*)d_in[11];

    const int B = in_sizes[0] / (NHAND * FIN);
    float* x3_out = (float*)d_out;
    float* fc_out = x3_out + (size_t)B * NHAND * FOUT;

    handnet_fused_kernel<<<B, NTHREADS>>>(x, A1, A2, A3, W1, b1, W2, b2,
                                          W3, b3, fcW, fcb, x3_out, fc_out);
}